// round 10
// baseline (speedup 1.0000x reference)
#include <cuda_runtime.h>
#include <math.h>

// ModifiedChamferLoss: H=W=M=512, N=H*W=262144
// d_in[0]=prob_map [262144] f32, d_in[1]=gt [512,2] f32 (d_in[2] unused; coords from index)
// out: scalar f32
//
// Single launch, 1088 blocks x 256 threads.
//  - blocks 0..63   : term2, one GT per warp. s = 1/(p^4+eps') >= ~1, so any achieved
//                     upper bound U restricts winners to d <= U*(1+eps'): scan a 32x16
//                     box, coverage check, exact square-expansion fallback (~1%).
//  - blocks 64..1087: term1, one 16x16 pixel tile each (1 px/thread); GT candidates
//                     pruned by triangle inequality (keep iff d(center,g) <= dmin + 2r).
//  - last block (persistent u64 modular ticket -> replay-safe, no init) reduces partials.

#define MPTS  512
#define NB2B  64                  /* term2 blocks (8 warps each)  */
#define NB1   1024                /* term1 tile blocks (16x16 px) */
#define NBTOT (NB2B + NB1)
#define TPB   256
#define FULLM 0xffffffffu

#define EPSF        1e-6f
#define MAXD_F      724.07733f          /* sqrt(512^2+512^2) */
#define MAXD2_F     524288.0f
#define EPS_OVER_MD 1.3810683e-9f       /* 1e-6f / 724.07733f */

typedef unsigned long long ull;

__device__ __forceinline__ ull pk2(float lo, float hi) {
    ull r; asm("mov.b64 %0, {%1, %2};" : "=l"(r) : "f"(lo), "f"(hi)); return r;
}
#define UNPK2(a, b, v) asm("mov.b64 {%0, %1}, %2;" : "=f"(a), "=f"(b) : "l"(v))
__device__ __forceinline__ ull add2(ull a, ull b) {
    ull r; asm("add.rn.f32x2 %0, %1, %2;" : "=l"(r) : "l"(a), "l"(b)); return r;
}
__device__ __forceinline__ ull mul2(ull a, ull b) {
    ull r; asm("mul.rn.f32x2 %0, %1, %2;" : "=l"(r) : "l"(a), "l"(b)); return r;
}
__device__ __forceinline__ ull fma2(ull a, ull b, ull c) {
    ull r; asm("fma.rn.f32x2 %0, %1, %2, %3;" : "=l"(r) : "l"(a), "l"(b), "l"(c)); return r;
}

__device__ float g_part_pd[NB1];   // per-term1-block partial: sum p*min_d   (plain stores)
__device__ float g_part_p[NB1];    // per-term1-block partial: sum p
__device__ int   g_min2[MPTS];     // per-GT min candidate^2 (float bits), plain stores
__device__ ull   g_done;           // persistent ticket; last block via modulo

__global__ void __launch_bounds__(TPB)
chamfer_all(const float* __restrict__ prob, const float* __restrict__ gt,
            float* __restrict__ out)
{
    const int tid  = threadIdx.x;
    const int lane = tid & 31;
    const int wid  = tid >> 5;
    __shared__ unsigned s_last;

    if (blockIdx.x < NB2B) {
        // ========== term2: one GT point per warp, 32(w) x 16(h) seed box ==========
        const int j  = (blockIdx.x << 3) + wid;            // 0..511
        const float gy = __ldg(&gt[2 * j]);
        const float gx = __ldg(&gt[2 * j + 1]);
        const int ry = min(max(__float2int_rn(gy), 0), 511);
        const int rx = min(max(__float2int_rn(gx), 0), 511);
        const int r0 = min(max(ry - 7, 0), 496);           // 16-row box
        const int c0 = min(max(rx - 15, 0), 480);          // 32-col box

        const int   col = c0 + lane;
        const float dxl = (float)col - gx;
        const float dx2 = dxl * dxl;
        float cmin2 = MAXD2_F;
        #pragma unroll                                     // full: 16 loads in flight
        for (int u = 0; u < 16; ++u) {
            int   r   = r0 + u;
            float p   = __ldg(&prob[r * 512 + col]);
            float dyl = (float)r - gy;
            float d2  = fmaf(dyl, dyl, dx2);
            float p2  = p * p;
            float s   = 1.0f / (p2 * p2 + EPS_OVER_MD);
            float cand = fminf((sqrtf(d2) + EPSF) * s, MAXD_F);
            cmin2 = fminf(cmin2, cand * cand);
        }
        cmin2 = __uint_as_float(__reduce_min_sync(FULLM, __float_as_uint(cmin2)));

        // coverage radius; image-edge sides cover everything beyond them
        float top = (r0 > 0)        ? (gy - (float)r0)        : 1e9f;
        float bot = (r0 + 15 < 511) ? ((float)(r0 + 15) - gy) : 1e9f;
        float lef = (c0 > 0)        ? (gx - (float)c0)        : 1e9f;
        float rig = (c0 + 31 < 511) ? ((float)(c0 + 31) - gx) : 1e9f;
        float rcov = fminf(fminf(top, bot), fminf(lef, rig));

        // cand >= d/(1+eps') -> winners lie within U*(1+eps') of the GT.
        if (cmin2 > rcov * rcov * 0.98f) {     // exact fallback (rare)
            int W   = (int)ceilf(sqrtf(cmin2) * 1.001f) + 1;
            int rr0 = max(0, ry - W), rr1 = min(511, ry + W);
            int cc0 = max(0, rx - W), cc1 = min(511, rx + W);
            for (int r = rr0; r <= rr1; ++r) {
                float dyl = (float)r - gy;
                float dy2 = dyl * dyl;
                for (int c = cc0 + lane; c <= cc1; c += 32) {
                    float p   = prob[r * 512 + c];
                    float dxe = (float)c - gx;
                    float d2  = fmaf(dxe, dxe, dy2);
                    float p2  = p * p;
                    float s   = 1.0f / (p2 * p2 + EPS_OVER_MD);
                    float cand = fminf((sqrtf(d2) + EPSF) * s, MAXD_F);
                    cmin2 = fminf(cmin2, cand * cand);
                }
            }
            cmin2 = __uint_as_float(__reduce_min_sync(FULLM, __float_as_uint(cmin2)));
        }
        if (lane == 0) g_min2[j] = __float_as_int(cmin2);   // plain store
    } else {
        // ========== term1: 16x16 tile (1 px/thread); triangle-inequality GT pruning ==========
        __shared__ __align__(16) float s_cgy[MPTS + 2];   // negated, compacted (+sentinel pad)
        __shared__ __align__(16) float s_cgx[MPTS + 2];
        __shared__ float s_wred[8];
        __shared__ int   s_wcA[8], s_wcB[8];
        __shared__ float r_pd[8], r_p[8];

        const int b1  = blockIdx.x - NB2B;
        const int ty0 = (b1 >> 5) << 4;          // 32x32 grid of 16x16 tiles
        const int tx0 = (b1 & 31) << 4;
        const float cy = (float)ty0 + 7.5f, cx = (float)tx0 + 7.5f;

        // hoist this thread's pixel + prob load (independent of phase A -> overlap latency)
        const int y0i = ty0 + (tid >> 4), x0i = tx0 + (tid & 15);
        const float p0 = prob[y0i * 512 + x0i];

        // phase A: each thread tests 2 GT points. r_tile = sqrt(7.5^2+7.5^2)=10.607
        float2 gA = ((const float2*)gt)[tid];
        float2 gB = ((const float2*)gt)[tid + 256];
        float dyA = cy - gA.x, dxA = cx - gA.y;
        float dyB = cy - gB.x, dxB = cx - gB.y;
        float dcA = sqrtf(fmaf(dyA, dyA, dxA * dxA));
        float dcB = sqrtf(fmaf(dyB, dyB, dxB * dxB));

        float m = fminf(dcA, dcB);
        #pragma unroll
        for (int o = 16; o; o >>= 1) m = fminf(m, __shfl_down_sync(FULLM, m, o));
        if (lane == 0) s_wred[wid] = m;
        __syncthreads();
        float dmin = s_wred[0];
        #pragma unroll
        for (int w = 1; w < 8; ++w) dmin = fminf(dmin, s_wred[w]);
        const float thr = dmin + 21.72f;         // 2*10.607 + 0.5 slack

        bool keepA = dcA <= thr, keepB = dcB <= thr;
        unsigned balA = __ballot_sync(FULLM, keepA);
        unsigned balB = __ballot_sync(FULLM, keepB);
        if (lane == 0) { s_wcA[wid] = __popc(balA); s_wcB[wid] = __popc(balB); }
        __syncthreads();
        int baseA = 0, totA = 0, baseB = 0, totB = 0;
        #pragma unroll
        for (int w = 0; w < 8; ++w) {
            int a = s_wcA[w], b = s_wcB[w];
            totA += a; totB += b;
            if (w < wid) { baseA += a; baseB += b; }
        }
        const int ncand = totA + totB;
        if (keepA) {
            int pos = baseA + __popc(balA & ((1u << lane) - 1u));
            s_cgy[pos] = -gA.x; s_cgx[pos] = -gA.y;
        }
        if (keepB) {
            int pos = totA + baseB + __popc(balB & ((1u << lane) - 1u));
            s_cgy[pos] = -gB.x; s_cgx[pos] = -gB.y;
        }
        if (tid == 0) {   // sentinel pad (d^2 ~ 1e14, never the min) -> no extra barrier
            s_cgy[ncand] = 1e7f; s_cgx[ncand] = 1e7f;
            s_cgy[ncand + 1] = 1e7f; s_cgx[ncand + 1] = 1e7f;
        }
        __syncthreads();
        const int np = (ncand + 1) & ~1;

        // phase B: 1 pixel per thread, 2 candidates per step
        const ull yy0 = pk2((float)y0i, (float)y0i);
        const ull xx0 = pk2((float)x0i, (float)x0i);

        float ma = 3.4e38f, mb = 3.4e38f;
        #pragma unroll 2
        for (int j = 0; j < np; j += 2) {
            ull gyv = *(const ull*)&s_cgy[j];
            ull gxv = *(const ull*)&s_cgx[j];
            ull dyv = add2(gyv, yy0);
            ull dxv = add2(gxv, xx0);
            ull d2  = fma2(dyv, dyv, mul2(dxv, dxv));
            float a, b; UNPK2(a, b, d2);
            ma = fminf(ma, a); mb = fminf(mb, b);
        }

        float v_pd = p0 * sqrtf(fminf(ma, mb));
        float v_p  = p0;
        #pragma unroll
        for (int o = 16; o; o >>= 1) {
            v_pd += __shfl_down_sync(FULLM, v_pd, o);
            v_p  += __shfl_down_sync(FULLM, v_p,  o);
        }
        if (lane == 0) { r_pd[wid] = v_pd; r_p[wid] = v_p; }
        __syncthreads();
        if (tid == 0) {
            float a = 0.0f, b = 0.0f;
            #pragma unroll
            for (int w = 0; w < 8; ++w) { a += r_pd[w]; b += r_p[w]; }
            g_part_pd[b1] = a;      // plain stores, no init needed
            g_part_p[b1]  = b;
        }
    }

    // ========== fused finalize: last block of THIS launch reduces and writes out ==========
    __syncthreads();
    if (tid == 0) {
        __threadfence();                       // publish stores before the ticket
        ull old = atomicAdd(&g_done, 1ull);
        s_last = ((old % (ull)NBTOT) == (ull)(NBTOT - 1)) ? 1u : 0u;
    }
    __syncthreads();
    if (s_last) {
        __threadfence();                       // acquire all other blocks' stores
        float v0 = sqrtf(__int_as_float(((volatile int*)g_min2)[tid]))
                 + sqrtf(__int_as_float(((volatile int*)g_min2)[tid + 256]));
        float v1 = 0.0f, v2 = 0.0f;
        #pragma unroll
        for (int q = 0; q < 4; ++q) {
            v1 += ((volatile float*)g_part_pd)[tid + 256 * q];
            v2 += ((volatile float*)g_part_p)[tid + 256 * q];
        }
        #pragma unroll
        for (int o = 16; o; o >>= 1) {
            v0 += __shfl_down_sync(FULLM, v0, o);
            v1 += __shfl_down_sync(FULLM, v1, o);
            v2 += __shfl_down_sync(FULLM, v2, o);
        }
        __shared__ float rf0[8], rf1[8], rf2[8];
        if (lane == 0) { rf0[wid] = v0; rf1[wid] = v1; rf2[wid] = v2; }
        __syncthreads();
        if (tid == 0) {
            float t2 = 0.0f, spd = 0.0f, sp = 0.0f;
            #pragma unroll
            for (int w = 0; w < 8; ++w) { t2 += rf0[w]; spd += rf1[w]; sp += rf2[w]; }
            t2 *= (1.0f / (float)MPTS);
            out[0] = spd / (sp + EPSF) + t2;
        }
    }
}

extern "C" void kernel_launch(void* const* d_in, const int* in_sizes, int n_in,
                              void* d_out, int out_size)
{
    const float* prob = (const float*)d_in[0];
    const float* gt   = (const float*)d_in[1];
    (void)in_sizes; (void)n_in; (void)out_size;

    chamfer_all<<<NBTOT, TPB>>>(prob, gt, (float*)d_out);
}

// round 11
// speedup vs baseline: 1.0025x; 1.0025x over previous
#include <cuda_runtime.h>
#include <math.h>

// ModifiedChamferLoss: H=W=M=512, N=H*W=262144
// d_in[0]=prob_map [262144] f32, d_in[1]=gt [512,2] f32 (d_in[2] unused; coords from index)
// out: scalar f32
//
// Single launch, 576 blocks x 256 threads (single wave at 6 blocks/SM).
//  - blocks 0..63  : term2, one GT per warp. s = 1/(p^4+eps') >= ~1, so any achieved
//                    upper bound U restricts winners to d <= U*(1+eps'): 32x16 box scan,
//                    coverage check, exact square-expansion fallback (~1%).
//  - blocks 64..575: term1, one 16(w)x32(h) pixel tile (2 px/thread, rows +16 share dx^2);
//                    GT candidates pruned by triangle inequality.
//  - last block (persistent u64 modular ticket -> replay-safe, no init) reduces partials.

#define MPTS  512
#define NB2B  64                  /* term2 blocks (8 warps each)     */
#define NB1   512                 /* term1 tile blocks (16w x 32h)   */
#define NBTOT (NB2B + NB1)
#define TPB   256
#define FULLM 0xffffffffu

#define EPSF        1e-6f
#define MAXD_F      724.07733f          /* sqrt(512^2+512^2) */
#define MAXD2_F     524288.0f
#define EPS_OVER_MD 1.3810683e-9f       /* 1e-6f / 724.07733f */

typedef unsigned long long ull;

__device__ __forceinline__ ull pk2(float lo, float hi) {
    ull r; asm("mov.b64 %0, {%1, %2};" : "=l"(r) : "f"(lo), "f"(hi)); return r;
}
#define UNPK2(a, b, v) asm("mov.b64 {%0, %1}, %2;" : "=f"(a), "=f"(b) : "l"(v))
__device__ __forceinline__ ull add2(ull a, ull b) {
    ull r; asm("add.rn.f32x2 %0, %1, %2;" : "=l"(r) : "l"(a), "l"(b)); return r;
}
__device__ __forceinline__ ull mul2(ull a, ull b) {
    ull r; asm("mul.rn.f32x2 %0, %1, %2;" : "=l"(r) : "l"(a), "l"(b)); return r;
}
__device__ __forceinline__ ull fma2(ull a, ull b, ull c) {
    ull r; asm("fma.rn.f32x2 %0, %1, %2, %3;" : "=l"(r) : "l"(a), "l"(b), "l"(c)); return r;
}

__device__ float g_part_pd[NB1];   // per-term1-block partial: sum p*min_d   (plain stores)
__device__ float g_part_p[NB1];    // per-term1-block partial: sum p
__device__ int   g_min2[MPTS];     // per-GT min candidate^2 (float bits), plain stores
__device__ ull   g_done;           // persistent ticket; last block via modulo

__global__ void __launch_bounds__(TPB)
chamfer_all(const float* __restrict__ prob, const float* __restrict__ gt,
            float* __restrict__ out)
{
    const int tid  = threadIdx.x;
    const int lane = tid & 31;
    const int wid  = tid >> 5;
    __shared__ unsigned s_last;

    if (blockIdx.x < NB2B) {
        // ========== term2: one GT point per warp, 32(w) x 16(h) seed box ==========
        const int j  = (blockIdx.x << 3) + wid;            // 0..511
        const float gy = __ldg(&gt[2 * j]);
        const float gx = __ldg(&gt[2 * j + 1]);
        const int ry = min(max(__float2int_rn(gy), 0), 511);
        const int rx = min(max(__float2int_rn(gx), 0), 511);
        const int r0 = min(max(ry - 7, 0), 496);           // 16-row box
        const int c0 = min(max(rx - 15, 0), 480);          // 32-col box

        const int   col = c0 + lane;
        const float dxl = (float)col - gx;
        const float dx2 = dxl * dxl;
        float cmin2 = MAXD2_F;
        #pragma unroll                                     // 16 loads in flight
        for (int u = 0; u < 16; ++u) {
            int   r   = r0 + u;
            float p   = __ldg(&prob[r * 512 + col]);
            float dyl = (float)r - gy;
            float d2  = fmaf(dyl, dyl, dx2);
            float p2  = p * p;
            float s   = 1.0f / (p2 * p2 + EPS_OVER_MD);
            float cand = fminf((sqrtf(d2) + EPSF) * s, MAXD_F);
            cmin2 = fminf(cmin2, cand * cand);
        }
        cmin2 = __uint_as_float(__reduce_min_sync(FULLM, __float_as_uint(cmin2)));

        // coverage radius; image-edge sides cover everything beyond them
        float top = (r0 > 0)        ? (gy - (float)r0)        : 1e9f;
        float bot = (r0 + 15 < 511) ? ((float)(r0 + 15) - gy) : 1e9f;
        float lef = (c0 > 0)        ? (gx - (float)c0)        : 1e9f;
        float rig = (c0 + 31 < 511) ? ((float)(c0 + 31) - gx) : 1e9f;
        float rcov = fminf(fminf(top, bot), fminf(lef, rig));

        // cand >= d/(1+eps') -> winners lie within U*(1+eps') of the GT.
        if (cmin2 > rcov * rcov * 0.98f) {     // exact fallback (rare)
            int W   = (int)ceilf(sqrtf(cmin2) * 1.001f) + 1;
            int rr0 = max(0, ry - W), rr1 = min(511, ry + W);
            int cc0 = max(0, rx - W), cc1 = min(511, rx + W);
            for (int r = rr0; r <= rr1; ++r) {
                float dyl = (float)r - gy;
                float dy2 = dyl * dyl;
                for (int c = cc0 + lane; c <= cc1; c += 32) {
                    float p   = prob[r * 512 + c];
                    float dxe = (float)c - gx;
                    float d2  = fmaf(dxe, dxe, dy2);
                    float p2  = p * p;
                    float s   = 1.0f / (p2 * p2 + EPS_OVER_MD);
                    float cand = fminf((sqrtf(d2) + EPSF) * s, MAXD_F);
                    cmin2 = fminf(cmin2, cand * cand);
                }
            }
            cmin2 = __uint_as_float(__reduce_min_sync(FULLM, __float_as_uint(cmin2)));
        }
        if (lane == 0) g_min2[j] = __float_as_int(cmin2);   // plain store
    } else {
        // ========== term1: 16(w) x 32(h) tile, 2 px/thread; triangle-ineq GT pruning ==========
        __shared__ __align__(16) float s_cgy[MPTS + 4];   // negated, compacted (+sentinels)
        __shared__ __align__(16) float s_cgx[MPTS + 4];
        __shared__ float s_wred[8];
        __shared__ int   s_wcA[8], s_wcB[8];
        __shared__ float r_pd[8], r_p[8];

        const int b1  = blockIdx.x - NB2B;
        const int ty0 = (b1 >> 5) << 5;          // 16 tile-rows of 32 px
        const int tx0 = (b1 & 31) << 4;          // 32 tile-cols of 16 px
        const float cy = (float)ty0 + 15.5f, cx = (float)tx0 + 7.5f;

        // hoist pixel loads (independent of phase A -> overlap global latency)
        const int y0i = ty0 + (tid >> 4), x0i = tx0 + (tid & 15);
        const int i0  = y0i * 512 + x0i;
        const float p0 = prob[i0];
        const float p1 = prob[i0 + 16 * 512];

        // phase A: 2 GT/thread. r_tile = sqrt(7.5^2+15.5^2)=17.22 -> thr = dmin+34.94
        float2 gA = ((const float2*)gt)[tid];
        float2 gB = ((const float2*)gt)[tid + 256];
        float dyA = cy - gA.x, dxA = cx - gA.y;
        float dyB = cy - gB.x, dxB = cx - gB.y;
        float dcA = sqrtf(fmaf(dyA, dyA, dxA * dxA));
        float dcB = sqrtf(fmaf(dyB, dyB, dxB * dxB));

        // REDUX.MIN on float bits (nonneg -> order-preserving): 1 instr vs 5 shfls
        unsigned mbits = __reduce_min_sync(FULLM, __float_as_uint(fminf(dcA, dcB)));
        if (lane == 0) s_wred[wid] = __uint_as_float(mbits);
        __syncthreads();
        float dmin = s_wred[0];
        #pragma unroll
        for (int w = 1; w < 8; ++w) dmin = fminf(dmin, s_wred[w]);
        const float thr = dmin + 34.94f;

        bool keepA = dcA <= thr, keepB = dcB <= thr;
        unsigned balA = __ballot_sync(FULLM, keepA);
        unsigned balB = __ballot_sync(FULLM, keepB);
        if (lane == 0) { s_wcA[wid] = __popc(balA); s_wcB[wid] = __popc(balB); }
        __syncthreads();
        int baseA = 0, totA = 0, baseB = 0, totB = 0;
        #pragma unroll
        for (int w = 0; w < 8; ++w) {
            int a = s_wcA[w], b = s_wcB[w];
            totA += a; totB += b;
            if (w < wid) { baseA += a; baseB += b; }
        }
        const int ncand = totA + totB;
        if (keepA) {
            int pos = baseA + __popc(balA & ((1u << lane) - 1u));
            s_cgy[pos] = -gA.x; s_cgx[pos] = -gA.y;
        }
        if (keepB) {
            int pos = totA + baseB + __popc(balB & ((1u << lane) - 1u));
            s_cgy[pos] = -gB.x; s_cgx[pos] = -gB.y;
        }
        if (tid == 0) {   // sentinels (d^2 ~1e14, never the min) pad to multiple of 4
            #pragma unroll
            for (int q = 0; q < 4; ++q) { s_cgy[ncand + q] = 1e7f; s_cgx[ncand + q] = 1e7f; }
        }
        __syncthreads();
        const int np4 = (ncand + 3) & ~3;

        // phase B: 2 rows (y, y+16) share dx^2; 4 GT per iteration
        const ull yy0 = pk2((float)y0i, (float)y0i);
        const ull yy1 = pk2((float)(y0i + 16), (float)(y0i + 16));
        const ull xx0 = pk2((float)x0i, (float)x0i);

        float ma0 = 3.4e38f, mb0 = 3.4e38f, ma1 = 3.4e38f, mb1 = 3.4e38f;
        for (int j = 0; j < np4; j += 4) {
            ull gy01 = *(const ull*)&s_cgy[j];
            ull gx01 = *(const ull*)&s_cgx[j];
            ull gy23 = *(const ull*)&s_cgy[j + 2];
            ull gx23 = *(const ull*)&s_cgx[j + 2];
            ull dx01 = add2(gx01, xx0);
            ull dx23 = add2(gx23, xx0);
            ull xs01 = mul2(dx01, dx01);
            ull xs23 = mul2(dx23, dx23);
            {
                ull dyv = add2(gy01, yy0);
                ull d2  = fma2(dyv, dyv, xs01);
                float a, b; UNPK2(a, b, d2);
                ma0 = fminf(ma0, a); mb0 = fminf(mb0, b);
            }
            {
                ull dyv = add2(gy01, yy1);
                ull d2  = fma2(dyv, dyv, xs01);
                float a, b; UNPK2(a, b, d2);
                ma1 = fminf(ma1, a); mb1 = fminf(mb1, b);
            }
            {
                ull dyv = add2(gy23, yy0);
                ull d2  = fma2(dyv, dyv, xs23);
                float a, b; UNPK2(a, b, d2);
                ma0 = fminf(ma0, a); mb0 = fminf(mb0, b);
            }
            {
                ull dyv = add2(gy23, yy1);
                ull d2  = fma2(dyv, dyv, xs23);
                float a, b; UNPK2(a, b, d2);
                ma1 = fminf(ma1, a); mb1 = fminf(mb1, b);
            }
        }

        float v_pd = p0 * sqrtf(fminf(ma0, mb0)) + p1 * sqrtf(fminf(ma1, mb1));
        float v_p  = p0 + p1;
        #pragma unroll
        for (int o = 16; o; o >>= 1) {
            v_pd += __shfl_down_sync(FULLM, v_pd, o);
            v_p  += __shfl_down_sync(FULLM, v_p,  o);
        }
        if (lane == 0) { r_pd[wid] = v_pd; r_p[wid] = v_p; }
        __syncthreads();
        if (tid == 0) {
            float a = 0.0f, b = 0.0f;
            #pragma unroll
            for (int w = 0; w < 8; ++w) { a += r_pd[w]; b += r_p[w]; }
            g_part_pd[b1] = a;      // plain stores, no init needed
            g_part_p[b1]  = b;
        }
    }

    // ========== fused finalize: last block of THIS launch reduces and writes out ==========
    __syncthreads();
    if (tid == 0) {
        __threadfence();                       // publish stores before the ticket
        ull old = atomicAdd(&g_done, 1ull);
        s_last = ((old % (ull)NBTOT) == (ull)(NBTOT - 1)) ? 1u : 0u;
    }
    __syncthreads();
    if (s_last) {
        __threadfence();                       // acquire all other blocks' stores
        float v0 = sqrtf(__int_as_float(((volatile int*)g_min2)[tid]))
                 + sqrtf(__int_as_float(((volatile int*)g_min2)[tid + 256]));
        float v1 = ((volatile float*)g_part_pd)[tid] + ((volatile float*)g_part_pd)[tid + 256];
        float v2 = ((volatile float*)g_part_p)[tid]  + ((volatile float*)g_part_p)[tid + 256];
        #pragma unroll
        for (int o = 16; o; o >>= 1) {
            v0 += __shfl_down_sync(FULLM, v0, o);
            v1 += __shfl_down_sync(FULLM, v1, o);
            v2 += __shfl_down_sync(FULLM, v2, o);
        }
        __shared__ float rf0[8], rf1[8], rf2[8];
        if (lane == 0) { rf0[wid] = v0; rf1[wid] = v1; rf2[wid] = v2; }
        __syncthreads();
        if (tid == 0) {
            float t2 = 0.0f, spd = 0.0f, sp = 0.0f;
            #pragma unroll
            for (int w = 0; w < 8; ++w) { t2 += rf0[w]; spd += rf1[w]; sp += rf2[w]; }
            t2 *= (1.0f / (float)MPTS);
            out[0] = spd / (sp + EPSF) + t2;
        }
    }
}

extern "C" void kernel_launch(void* const* d_in, const int* in_sizes, int n_in,
                              void* d_out, int out_size)
{
    const float* prob = (const float*)d_in[0];
    const float* gt   = (const float*)d_in[1];
    (void)in_sizes; (void)n_in; (void)out_size;

    chamfer_all<<<NBTOT, TPB>>>(prob, gt, (float*)d_out);
}